// round 1
// baseline (speedup 1.0000x reference)
#include <cuda_runtime.h>

// Two-reduction over 8M points:
//   g   = sum_i exp(-0.5*((|p_i - cam|-2)/4)^2) / (4*sqrt(2*pi))
//   cnt = # points strictly inside rotated+translated triangle
// out[0] = 1/(g+eps) + 1/(cnt+eps)

#define BLOCKS  1184
#define THREADS 256

__device__ float g_partial_gauss[BLOCKS];
__device__ float g_partial_count[BLOCKS];

#define GAUSS_NORM 0.09973557010f   // 1 / (4 * sqrt(2*pi))
#define EPSV 1e-06f

__global__ __launch_bounds__(THREADS, 8)
void reduce_kernel(const float4* __restrict__ pts4, int n4,
                   const float* __restrict__ cam)
{
    // camera + triangle geometry (uniform per thread; cheap)
    const float cx = cam[0];
    const float cy = cam[1];
    const float yaw = cam[2];
    float s, c;
    __sincosf(yaw, &s, &c);

    // POLY = {(0,0),(2,7),(-2,7)}, verts = rot(POLY) + (cx,cy)
    const float v0x = cx,                 v0y = cy;
    const float v1x = 2.f*c - 7.f*s + cx, v1y = 2.f*s + 7.f*c + cy;
    const float v2x = -2.f*c - 7.f*s + cx, v2y = -2.f*s + 7.f*c + cy;

    const float e0x = v1x - v0x, e0y = v1y - v0y;
    const float e1x = v2x - v1x, e1y = v2y - v1y;
    const float e2x = v0x - v2x, e2y = v0y - v2y;

    float acc_g = 0.f;
    int   acc_c = 0;

    const int stride = BLOCKS * THREADS;
    for (int i = blockIdx.x * THREADS + threadIdx.x; i < n4; i += stride) {
        float4 q = pts4[i];   // two points: (q.x,q.y) and (q.z,q.w)

        // ---- point 0 ----
        {
            float dx = q.x - cx, dy = q.y - cy;
            float d = sqrtf(fmaf(dx, dx, dy * dy));
            float t = (d - 2.0f) * 0.25f;
            acc_g += __expf(-0.5f * t * t);

            float c0 = e0x * (q.y - v0y) - e0y * (q.x - v0x);
            float c1 = e1x * (q.y - v1y) - e1y * (q.x - v1x);
            float c2 = e2x * (q.y - v2y) - e2y * (q.x - v2x);
            bool inside = (c0 > 0.f && c1 > 0.f && c2 > 0.f) ||
                          (c0 < 0.f && c1 < 0.f && c2 < 0.f);
            acc_c += inside ? 1 : 0;
        }
        // ---- point 1 ----
        {
            float dx = q.z - cx, dy = q.w - cy;
            float d = sqrtf(fmaf(dx, dx, dy * dy));
            float t = (d - 2.0f) * 0.25f;
            acc_g += __expf(-0.5f * t * t);

            float c0 = e0x * (q.w - v0y) - e0y * (q.z - v0x);
            float c1 = e1x * (q.w - v1y) - e1y * (q.z - v1x);
            float c2 = e2x * (q.w - v2y) - e2y * (q.z - v2x);
            bool inside = (c0 > 0.f && c1 > 0.f && c2 > 0.f) ||
                          (c0 < 0.f && c1 < 0.f && c2 < 0.f);
            acc_c += inside ? 1 : 0;
        }
    }

    acc_g *= GAUSS_NORM;

    // block reduction (deterministic: fixed tree)
    __shared__ float sg[THREADS];
    __shared__ int   sc[THREADS];
    sg[threadIdx.x] = acc_g;
    sc[threadIdx.x] = acc_c;
    __syncthreads();
    #pragma unroll
    for (int off = THREADS / 2; off > 0; off >>= 1) {
        if (threadIdx.x < off) {
            sg[threadIdx.x] += sg[threadIdx.x + off];
            sc[threadIdx.x] += sc[threadIdx.x + off];
        }
        __syncthreads();
    }
    if (threadIdx.x == 0) {
        g_partial_gauss[blockIdx.x] = sg[0];
        g_partial_count[blockIdx.x] = (float)sc[0];
    }
}

__global__ void finalize_kernel(float* __restrict__ out)
{
    __shared__ float sg[1024];
    __shared__ float sc[1024];
    float ag = 0.f, ac = 0.f;
    for (int i = threadIdx.x; i < BLOCKS; i += 1024) {
        ag += g_partial_gauss[i];
        ac += g_partial_count[i];
    }
    sg[threadIdx.x] = ag;
    sc[threadIdx.x] = ac;
    __syncthreads();
    #pragma unroll
    for (int off = 512; off > 0; off >>= 1) {
        if (threadIdx.x < off) {
            sg[threadIdx.x] += sg[threadIdx.x + off];
            sc[threadIdx.x] += sc[threadIdx.x + off];
        }
        __syncthreads();
    }
    if (threadIdx.x == 0) {
        out[0] = 1.0f / (sg[0] + EPSV) + 1.0f / (sc[0] + EPSV);
    }
}

extern "C" void kernel_launch(void* const* d_in, const int* in_sizes, int n_in,
                              void* d_out, int out_size)
{
    const float* points = (const float*)d_in[0];   // [N,2] float32
    const float* cam    = (const float*)d_in[1];   // [3]  float32
    float* out = (float*)d_out;

    int n_floats = in_sizes[0];       // 2*N
    int n4 = n_floats / 4;            // number of float4 (2 points each)

    reduce_kernel<<<BLOCKS, THREADS>>>((const float4*)points, n4, cam);
    finalize_kernel<<<1, 1024>>>(out);
}

// round 2
// speedup vs baseline: 1.3636x; 1.3636x over previous
#include <cuda_runtime.h>

// Fused single-kernel two-reduction over 8M points:
//   g   = sum_i exp(-0.5*((|p_i - cam|-2)/4)^2) / (4*sqrt(2*pi))
//   cnt = # points strictly inside rotated+translated CCW triangle
// out[0] = 1/(g+eps) + 1/(cnt+eps)

#define BLOCKS  1184
#define THREADS 256

__device__ float g_partial_gauss[BLOCKS];
__device__ float g_partial_count[BLOCKS];
__device__ int   g_ticket = 0;   // reset to 0 by the finalizing block each call

#define GAUSS_NORM 0.09973557010f   // 1 / (4 * sqrt(2*pi))
#define EPSV 1e-06f
// (d-2) scale folded into ex2 arg: exp(-0.5*((d-2)/4)^2) = ex2(-(K*(d-2))^2),
// K = sqrt(0.5*log2(e))/4 = 0.2123346587f
#define KFOLD 0.2123346587f

__device__ __forceinline__ float fast_sqrt(float x) {
    float r; asm("sqrt.approx.f32 %0, %1;" : "=f"(r) : "f"(x)); return r;
}
__device__ __forceinline__ float fast_ex2(float x) {
    float r; asm("ex2.approx.f32 %0, %1;" : "=f"(r) : "f"(x)); return r;
}

struct Geo {
    float cx, cy;
    float a0, b0, d0, a1, b1, d1, a2, b2, d2;  // cross_k(p) = a*px + b*py + d
};

__device__ __forceinline__ void body(const float px, const float py,
                                     const Geo& G, float& acc_g, int& acc_c)
{
    float dx = px - G.cx, dy = py - G.cy;
    float d  = fast_sqrt(fmaf(dx, dx, dy * dy));
    float w  = (d - 2.0f) * KFOLD;
    acc_g += fast_ex2(-w * w);

    float c0 = fmaf(G.a0, px, fmaf(G.b0, py, G.d0));
    float c1 = fmaf(G.a1, px, fmaf(G.b1, py, G.d1));
    float c2 = fmaf(G.a2, px, fmaf(G.b2, py, G.d2));
    acc_c += (c0 > 0.f && c1 > 0.f && c2 > 0.f) ? 1 : 0;
}

__global__ __launch_bounds__(THREADS, 8)
void fused_kernel(const float4* __restrict__ pts4, int n4,
                  const float* __restrict__ cam, int odd_point,
                  const float* __restrict__ pts_scalar,
                  float* __restrict__ out)
{
    // geometry setup (uniform)
    Geo G;
    G.cx = cam[0]; G.cy = cam[1];
    const float yaw = cam[2];
    float s, c;
    __sincosf(yaw, &s, &c);
    // POLY {(0,0),(2,7),(-2,7)} (CCW) rotated by yaw, translated by (cx,cy)
    const float v0x = G.cx,                     v0y = G.cy;
    const float v1x =  2.f*c - 7.f*s + G.cx,    v1y =  2.f*s + 7.f*c + G.cy;
    const float v2x = -2.f*c - 7.f*s + G.cx,    v2y = -2.f*s + 7.f*c + G.cy;
    // edge e_k = v_{k+1}-v_k ; cross_k = e_kx*(py-v_ky) - e_ky*(px-v_kx)
    //          = (-e_ky)*px + (e_kx)*py + (e_ky*v_kx - e_kx*v_ky)
    {
        float ex = v1x - v0x, ey = v1y - v0y;
        G.a0 = -ey; G.b0 = ex; G.d0 = ey * v0x - ex * v0y;
        ex = v2x - v1x; ey = v2y - v1y;
        G.a1 = -ey; G.b1 = ex; G.d1 = ey * v1x - ex * v1y;
        ex = v0x - v2x; ey = v0y - v2y;
        G.a2 = -ey; G.b2 = ex; G.d2 = ey * v2x - ex * v2y;
    }

    float acc_g = 0.f;
    int   acc_c = 0;

    const int stride  = BLOCKS * THREADS;
    const int tid0    = blockIdx.x * THREADS + threadIdx.x;
    const int stride4 = 4 * stride;

    // main loop: 4 independent LDG.128 front-batched per iteration
    int i = tid0;
    for (; i + 3 * stride < n4; i += stride4) {
        float4 q0 = pts4[i];
        float4 q1 = pts4[i + stride];
        float4 q2 = pts4[i + 2 * stride];
        float4 q3 = pts4[i + 3 * stride];
        body(q0.x, q0.y, G, acc_g, acc_c);  body(q0.z, q0.w, G, acc_g, acc_c);
        body(q1.x, q1.y, G, acc_g, acc_c);  body(q1.z, q1.w, G, acc_g, acc_c);
        body(q2.x, q2.y, G, acc_g, acc_c);  body(q2.z, q2.w, G, acc_g, acc_c);
        body(q3.x, q3.y, G, acc_g, acc_c);  body(q3.z, q3.w, G, acc_g, acc_c);
    }
    for (; i < n4; i += stride) {
        float4 q = pts4[i];
        body(q.x, q.y, G, acc_g, acc_c);  body(q.z, q.w, G, acc_g, acc_c);
    }
    // possible lone trailing point (N odd) — handled by one thread
    if (odd_point && blockIdx.x == 0 && threadIdx.x == 0) {
        body(pts_scalar[4 * n4], pts_scalar[4 * n4 + 1], G, acc_g, acc_c);
    }

    acc_g *= GAUSS_NORM;

    // block reduction (fixed tree -> deterministic)
    __shared__ float sg[THREADS];
    __shared__ int   sc[THREADS];
    sg[threadIdx.x] = acc_g;
    sc[threadIdx.x] = acc_c;
    __syncthreads();
    #pragma unroll
    for (int off = THREADS / 2; off > 0; off >>= 1) {
        if (threadIdx.x < off) {
            sg[threadIdx.x] += sg[threadIdx.x + off];
            sc[threadIdx.x] += sc[threadIdx.x + off];
        }
        __syncthreads();
    }

    __shared__ bool is_last;
    if (threadIdx.x == 0) {
        g_partial_gauss[blockIdx.x] = sg[0];
        g_partial_count[blockIdx.x] = (float)sc[0];
        __threadfence();
        int t = atomicAdd(&g_ticket, 1);
        is_last = (t == BLOCKS - 1);
    }
    __syncthreads();

    if (is_last) {
        __threadfence();
        // final reduction over BLOCKS partials, fixed order -> deterministic
        float ag = 0.f, ac = 0.f;
        for (int k = threadIdx.x; k < BLOCKS; k += THREADS) {
            ag += g_partial_gauss[k];
            ac += g_partial_count[k];
        }
        sg[threadIdx.x] = ag;
        sc[threadIdx.x] = 0;           // reuse sg for gauss, pack count in sg2
        __shared__ float sg2[THREADS];
        sg2[threadIdx.x] = ac;
        __syncthreads();
        #pragma unroll
        for (int off = THREADS / 2; off > 0; off >>= 1) {
            if (threadIdx.x < off) {
                sg[threadIdx.x]  += sg[threadIdx.x + off];
                sg2[threadIdx.x] += sg2[threadIdx.x + off];
            }
            __syncthreads();
        }
        if (threadIdx.x == 0) {
            out[0] = 1.0f / (sg[0] + EPSV) + 1.0f / (sg2[0] + EPSV);
            g_ticket = 0;   // re-arm for next graph replay
        }
    }
}

extern "C" void kernel_launch(void* const* d_in, const int* in_sizes, int n_in,
                              void* d_out, int out_size)
{
    const float* points = (const float*)d_in[0];   // [N,2] float32
    const float* cam    = (const float*)d_in[1];   // [3]  float32
    float* out = (float*)d_out;

    int n_floats  = in_sizes[0];          // 2*N
    int n4        = n_floats / 4;         // float4 groups (2 points each)
    int odd_point = ((n_floats / 2) & 1); // lone trailing point if N odd

    fused_kernel<<<BLOCKS, THREADS>>>((const float4*)points, n4, cam,
                                      odd_point, points, out);
}

// round 3
// speedup vs baseline: 1.5517x; 1.1379x over previous
#include <cuda_runtime.h>

// Fused single-kernel two-reduction over 8M points:
//   g   = sum_i exp(-0.5*((|p_i - cam|-2)/4)^2) / (4*sqrt(2*pi))
//   cnt = # points strictly inside rotated+translated CCW triangle
// out[0] = 1/(g+eps) + 1/(cnt+eps)

#define BLOCKS  592
#define THREADS 256
#define UNROLL  8

__device__ float g_partial_gauss[BLOCKS];
__device__ float g_partial_count[BLOCKS];
__device__ int   g_ticket = 0;   // reset to 0 by the finalizing block each call

#define GAUSS_NORM 0.09973557010f   // 1 / (4 * sqrt(2*pi))
#define EPSV 1e-06f
// exp(-0.5*((d-2)/4)^2) = ex2(-(K*d - 2K)^2), K = sqrt(0.5*log2(e))/4
#define KFOLD  0.2123346587f
#define KFOLD2 0.4246693174f        // 2*K

__device__ __forceinline__ float fast_sqrt(float x) {
    float r; asm("sqrt.approx.f32 %0, %1;" : "=f"(r) : "f"(x)); return r;
}
__device__ __forceinline__ float fast_ex2(float x) {
    float r; asm("ex2.approx.f32 %0, %1;" : "=f"(r) : "f"(x)); return r;
}

struct Geo {
    float cx, cy;
    float a0, b0, d0, a1, b1, d1, a2, b2, d2;  // cross_k(p) = a*px + b*py + d
};

__device__ __forceinline__ void body(const float px, const float py,
                                     const Geo& G, float& acc_g, float& acc_c)
{
    float dx = px - G.cx, dy = py - G.cy;
    float d  = fast_sqrt(fmaf(dx, dx, dy * dy));
    float w  = fmaf(d, KFOLD, -KFOLD2);          // K*(d-2)
    acc_g += fast_ex2(-w * w);

    float c0 = fmaf(G.a0, px, fmaf(G.b0, py, G.d0));
    float c1 = fmaf(G.a1, px, fmaf(G.b1, py, G.d1));
    float c2 = fmaf(G.a2, px, fmaf(G.b2, py, G.d2));
    float m  = fminf(fminf(c0, c1), c2);
    if (m > 0.0f) acc_c += 1.0f;                 // predicated FADD
}

__global__ __launch_bounds__(THREADS, 4)
void fused_kernel(const float4* __restrict__ pts4, int n4,
                  const float* __restrict__ cam, int odd_point,
                  const float* __restrict__ pts_scalar,
                  float* __restrict__ out)
{
    // geometry setup (uniform per thread)
    Geo G;
    G.cx = cam[0]; G.cy = cam[1];
    const float yaw = cam[2];
    float s, c;
    __sincosf(yaw, &s, &c);
    // POLY {(0,0),(2,7),(-2,7)} is CCW; rotation preserves orientation,
    // so "inside" <=> all three edge crosses > 0.
    const float v0x = G.cx,                      v0y = G.cy;
    const float v1x =  2.f*c - 7.f*s + G.cx,     v1y =  2.f*s + 7.f*c + G.cy;
    const float v2x = -2.f*c - 7.f*s + G.cx,     v2y = -2.f*s + 7.f*c + G.cy;
    {
        float ex = v1x - v0x, ey = v1y - v0y;
        G.a0 = -ey; G.b0 = ex; G.d0 = ey * v0x - ex * v0y;
        ex = v2x - v1x; ey = v2y - v1y;
        G.a1 = -ey; G.b1 = ex; G.d1 = ey * v1x - ex * v1y;
        ex = v0x - v2x; ey = v0y - v2y;
        G.a2 = -ey; G.b2 = ex; G.d2 = ey * v2x - ex * v2y;
    }

    // dual accumulators to split the FADD dependency chains
    float acc_g0 = 0.f, acc_g1 = 0.f;
    float acc_c0 = 0.f, acc_c1 = 0.f;

    const int stride  = BLOCKS * THREADS;
    const int tid0    = blockIdx.x * THREADS + threadIdx.x;
    const int strideU = UNROLL * stride;

    int i = tid0;
    for (; i + (UNROLL - 1) * stride < n4; i += strideU) {
        float4 q[UNROLL];
        #pragma unroll
        for (int u = 0; u < UNROLL; u++) q[u] = pts4[i + u * stride];
        #pragma unroll
        for (int u = 0; u < UNROLL; u++) {
            body(q[u].x, q[u].y, G, acc_g0, acc_c0);
            body(q[u].z, q[u].w, G, acc_g1, acc_c1);
        }
    }
    for (; i < n4; i += stride) {
        float4 q = pts4[i];
        body(q.x, q.y, G, acc_g0, acc_c0);
        body(q.z, q.w, G, acc_g1, acc_c1);
    }
    // lone trailing point if N odd
    if (odd_point && blockIdx.x == 0 && threadIdx.x == 0) {
        body(pts_scalar[4 * n4], pts_scalar[4 * n4 + 1], G, acc_g0, acc_c0);
    }

    float acc_g = (acc_g0 + acc_g1) * GAUSS_NORM;
    float acc_c = acc_c0 + acc_c1;

    // block reduction (fixed tree -> deterministic)
    __shared__ float sg[THREADS];
    __shared__ float sc[THREADS];
    sg[threadIdx.x] = acc_g;
    sc[threadIdx.x] = acc_c;
    __syncthreads();
    #pragma unroll
    for (int off = THREADS / 2; off > 0; off >>= 1) {
        if (threadIdx.x < off) {
            sg[threadIdx.x] += sg[threadIdx.x + off];
            sc[threadIdx.x] += sc[threadIdx.x + off];
        }
        __syncthreads();
    }

    __shared__ bool is_last;
    if (threadIdx.x == 0) {
        g_partial_gauss[blockIdx.x] = sg[0];
        g_partial_count[blockIdx.x] = sc[0];
        __threadfence();
        int t = atomicAdd(&g_ticket, 1);
        is_last = (t == BLOCKS - 1);
    }
    __syncthreads();

    if (is_last) {
        __threadfence();
        float ag = 0.f, ac = 0.f;
        for (int k = threadIdx.x; k < BLOCKS; k += THREADS) {
            ag += g_partial_gauss[k];
            ac += g_partial_count[k];
        }
        sg[threadIdx.x] = ag;
        sc[threadIdx.x] = ac;
        __syncthreads();
        #pragma unroll
        for (int off = THREADS / 2; off > 0; off >>= 1) {
            if (threadIdx.x < off) {
                sg[threadIdx.x] += sg[threadIdx.x + off];
                sc[threadIdx.x] += sc[threadIdx.x + off];
            }
            __syncthreads();
        }
        if (threadIdx.x == 0) {
            out[0] = 1.0f / (sg[0] + EPSV) + 1.0f / (sc[0] + EPSV);
            g_ticket = 0;   // re-arm for next graph replay
        }
    }
}

extern "C" void kernel_launch(void* const* d_in, const int* in_sizes, int n_in,
                              void* d_out, int out_size)
{
    const float* points = (const float*)d_in[0];   // [N,2] float32
    const float* cam    = (const float*)d_in[1];   // [3]  float32
    float* out = (float*)d_out;

    int n_floats  = in_sizes[0];          // 2*N
    int n4        = n_floats / 4;         // float4 groups (2 points each)
    int odd_point = ((n_floats / 2) & 1); // lone trailing point if N odd

    fused_kernel<<<BLOCKS, THREADS>>>((const float4*)points, n4, cam,
                                      odd_point, points, out);
}